// round 16
// baseline (speedup 1.0000x reference)
#include <cuda_runtime.h>
#include <math.h>
#include <stdint.h>

#define V_N 50000
#define E_N 800000
#define SCAN_B 196          /* 196*256 = 50176 >= V_N */
#define NTHR  (SCAN_B * 256)

__device__ int    g_hist[SCAN_B * 256];
__device__ int    g_start[V_N + 1];
__device__ int    g_cursor[V_N];
__device__ int    g_bsum[SCAN_B];
__device__ int    g_c0, g_c1, g_c2, g_c3, g_fin;   // zero-init; self-reset each launch
__device__ int    g_src[E_N];
__device__ float4 g_trig[(size_t)E_N * 2];   // sorted pos: [2p]=angle basis, [2p+1]=transporter
// W packed in mma-fragment order: index = ((ks*64 + ocol)*4 + t)*2 + r
__device__ uint32_t g_Wh[24 * 64 * 8];
__device__ uint32_t g_Wl[24 * 64 * 8];

// ---------------- helpers ----------------
__device__ __forceinline__ uint32_t pack_bf16(float e0, float e1) {
    uint32_t r;
    asm("cvt.rn.bf16x2.f32 %0, %1, %2;" : "=r"(r) : "f"(e1), "f"(e0));
    return r;
}

__device__ __forceinline__ void mma_bf16(float* d, const uint32_t* a, const uint32_t* b) {
    asm volatile(
        "mma.sync.aligned.m16n8k16.row.col.f32.bf16.bf16.f32 "
        "{%0,%1,%2,%3}, {%4,%5,%6,%7}, {%8,%9}, {%0,%1,%2,%3};"
        : "+f"(d[0]), "+f"(d[1]), "+f"(d[2]), "+f"(d[3])
        : "r"(a[0]), "r"(a[1]), "r"(a[2]), "r"(a[3]), "r"(b[0]), "r"(b[1]));
}

__device__ __forceinline__ void grid_sync(int* ctr) {
    __syncthreads();
    if (threadIdx.x == 0) {
        __threadfence();
        atomicAdd(ctr, 1);
        while (atomicAdd(ctr, 0) < SCAN_B) { }
    }
    __syncthreads();
    __threadfence();
}

// ---------------- persistent pre-kernel: zero+Wpack | hist | scan | scatter ----------------
__global__ __launch_bounds__(256) void pre_kernel(
    const int*   __restrict__ ei,
    const float* __restrict__ angles,
    const float* __restrict__ trans,
    const float* __restrict__ Wn,
    const float* __restrict__ Ks)
{
    __shared__ int sh[256];
    __shared__ int red[256];
    const int t   = threadIdx.x;
    const int b   = blockIdx.x;
    const int gid = b * 256 + t;

    // ---- P0: zero hist + pack W fragments ----
    g_hist[gid] = 0;
    if (gid < 24 * 64 * 4) {
        const int tt   = gid & 3;
        const int ocol = (gid >> 2) & 63;
        const int ks   = gid >> 8;
#pragma unroll
        for (int r = 0; r < 2; ++r) {
            const int k0 = 16 * ks + 8 * r;
            const float* wp = (k0 < 320)
                ? (Wn + (k0 >> 6) * 4096 + ocol * 64 + (k0 & 63) + 2 * tt)
                : (Ks + ocol * 64 + (k0 - 320) + 2 * tt);
            const float2 w = *reinterpret_cast<const float2*>(wp);
            const uint32_t hi = pack_bf16(w.x, w.y);
            const float h0 = __uint_as_float(hi << 16);
            const float h1 = __uint_as_float(hi & 0xffff0000u);
            const int widx = gid * 2 + r;
            g_Wh[widx] = hi;
            g_Wl[widx] = pack_bf16(w.x - h0, w.y - h1);
        }
    }
    grid_sync(&g_c0);

    // ---- P1: histogram ----
    for (int e = gid; e < E_N; e += NTHR)
        atomicAdd(&g_hist[ei[E_N + e]], 1);
    grid_sync(&g_c1);

    // ---- P2: scan ----
    {
        const int v = g_hist[gid];
        sh[t] = v;
        __syncthreads();
        for (int o = 1; o < 256; o <<= 1) {
            int u = (t >= o) ? sh[t - o] : 0;
            __syncthreads();
            sh[t] += u;
            __syncthreads();
        }
        if (t == 255) g_bsum[b] = sh[255];
        grid_sync(&g_c2);

        red[t] = (t < b) ? g_bsum[t] : 0;
        __syncthreads();
        for (int o = 128; o; o >>= 1) {
            if (t < o) red[t] += red[t + o];
            __syncthreads();
        }
        const int excl = sh[t] - v + red[0];
        if (gid < V_N) {
            g_start[gid]  = excl;
            g_cursor[gid] = excl;
            if (gid == V_N - 1) g_start[V_N] = excl + v;
        }
    }
    grid_sync(&g_c3);

    // ---- P3: scatter (trig precompute into sorted positions) ----
    for (int e = gid; e < E_N; e += NTHR) {
        const int tgt = ei[E_N + e];
        const int pos = atomicAdd(&g_cursor[tgt], 1);
        g_src[pos] = ei[e];
        float sa, ca, st, ct;
        __sincosf(angles[e], &sa, &ca);
        __sincosf(trans[e],  &st, &ct);
        g_trig[2 * pos]     = make_float4(ca, sa, fmaf(2.f * ca, ca, -1.f), 2.f * sa * ca);
        g_trig[2 * pos + 1] = make_float4(ct, st, fmaf(2.f * ct, ct, -1.f), 2.f * st * ct);
    }

    // ---- finalize: last CTA resets sync counters for the next graph replay ----
    __syncthreads();
    if (t == 0) {
        __threadfence();
        const int old = atomicAdd(&g_fin, 1);
        if (old == SCAN_B - 1) {
            g_c0 = 0; g_c1 = 0; g_c2 = 0; g_c3 = 0; g_fin = 0;
        }
    }
}

// ---------------- fused accum + GEMM + LN + nonlin + residual (R13 exact) ----------------
// M=32 tile -> 50KB smem -> 4 CTAs/SM (32 warps/SM) for gather latency hiding.
#define AP 196   /* smem pair stride (== 4 mod 32 -> conflict-free frag loads) */
#define MT 32    /* rows per CTA */

__global__ __launch_bounds__(256, 4) void fused_kernel(
    const float* __restrict__ x,
    const float* __restrict__ gamma,
    const float* __restrict__ beta,
    float* __restrict__ out)
{
    extern __shared__ uint32_t sm[];
    uint32_t* smh = sm;                   // hi: [MT][AP]
    uint32_t* sml = sm + MT * AP;         // lo: [MT][AP] (aliased by msg later)

    const int tid  = threadIdx.x;
    const int lane = tid & 31;
    const int wid  = tid >> 5;
    const int g    = lane >> 2;
    const int t    = lane & 3;
    const int h    = lane >> 4;
    const int l    = lane & 15;
    const int v0   = blockIdx.x * MT;
    const int ocol = 8 * wid + g;

    // ---- phase 1: per-vertex S accumulation straight into smem ----
#pragma unroll 1
    for (int k = 0; k < 4; ++k) {
        const int row = 4 * wid + k;
        const int v   = v0 + row;

        float4 S0 = make_float4(0.f, 0.f, 0.f, 0.f);
        float4 S1 = S0, S2 = S0, S3 = S0, S4 = S0;

        if (v < V_N) {
            const int jb = g_start[v];
            const int je = g_start[v + 1];
            for (int j = jb + h; j < je; j += 2) {
                const int    src = g_src[j];
                const float4 A   = g_trig[2 * j];
                const float4 T   = g_trig[2 * j + 1];
                float4 f = *reinterpret_cast<const float4*>(x + (size_t)src * 64 + 4 * l);
                if (l >= 4) {
                    const float cr = (l < 12) ? T.x : T.z;
                    const float sr = (l < 12) ? T.y : T.w;
                    const float a0 = cr * f.x - sr * f.y, b0 = sr * f.x + cr * f.y;
                    const float a1 = cr * f.z - sr * f.w, b1 = sr * f.z + cr * f.w;
                    f = make_float4(a0, b0, a1, b1);
                }
                S0.x += f.x;  S0.y += f.y;  S0.z += f.z;  S0.w += f.w;
                S1.x = fmaf(A.x, f.x, S1.x); S1.y = fmaf(A.x, f.y, S1.y);
                S1.z = fmaf(A.x, f.z, S1.z); S1.w = fmaf(A.x, f.w, S1.w);
                S2.x = fmaf(A.y, f.x, S2.x); S2.y = fmaf(A.y, f.y, S2.y);
                S2.z = fmaf(A.y, f.z, S2.z); S2.w = fmaf(A.y, f.w, S2.w);
                S3.x = fmaf(A.z, f.x, S3.x); S3.y = fmaf(A.z, f.y, S3.y);
                S3.z = fmaf(A.z, f.z, S3.z); S3.w = fmaf(A.z, f.w, S3.w);
                S4.x = fmaf(A.w, f.x, S4.x); S4.y = fmaf(A.w, f.y, S4.y);
                S4.z = fmaf(A.w, f.z, S4.z); S4.w = fmaf(A.w, f.w, S4.w);
            }
        }

        // merge halves
        S0.x += __shfl_xor_sync(0xffffffffu, S0.x, 16);
        S0.y += __shfl_xor_sync(0xffffffffu, S0.y, 16);
        S0.z += __shfl_xor_sync(0xffffffffu, S0.z, 16);
        S0.w += __shfl_xor_sync(0xffffffffu, S0.w, 16);
        S1.x += __shfl_xor_sync(0xffffffffu, S1.x, 16);
        S1.y += __shfl_xor_sync(0xffffffffu, S1.y, 16);
        S1.z += __shfl_xor_sync(0xffffffffu, S1.z, 16);
        S1.w += __shfl_xor_sync(0xffffffffu, S1.w, 16);
        S2.x += __shfl_xor_sync(0xffffffffu, S2.x, 16);
        S2.y += __shfl_xor_sync(0xffffffffu, S2.y, 16);
        S2.z += __shfl_xor_sync(0xffffffffu, S2.z, 16);
        S2.w += __shfl_xor_sync(0xffffffffu, S2.w, 16);
        S3.x += __shfl_xor_sync(0xffffffffu, S3.x, 16);
        S3.y += __shfl_xor_sync(0xffffffffu, S3.y, 16);
        S3.z += __shfl_xor_sync(0xffffffffu, S3.z, 16);
        S3.w += __shfl_xor_sync(0xffffffffu, S3.w, 16);
        S4.x += __shfl_xor_sync(0xffffffffu, S4.x, 16);
        S4.y += __shfl_xor_sync(0xffffffffu, S4.y, 16);
        S4.z += __shfl_xor_sync(0xffffffffu, S4.z, 16);
        S4.w += __shfl_xor_sync(0xffffffffu, S4.w, 16);

        if (h == 0) {
            const int base = row * AP + 2 * l;
            float4 Sb[5] = {S0, S1, S2, S3, S4};
#pragma unroll
            for (int b = 0; b < 5; ++b) {
                const uint32_t hi0 = pack_bf16(Sb[b].x, Sb[b].y);
                const uint32_t hi1 = pack_bf16(Sb[b].z, Sb[b].w);
                const float e0 = Sb[b].x - __uint_as_float(hi0 << 16);
                const float e1 = Sb[b].y - __uint_as_float(hi0 & 0xffff0000u);
                const float e2 = Sb[b].z - __uint_as_float(hi1 << 16);
                const float e3 = Sb[b].w - __uint_as_float(hi1 & 0xffff0000u);
                *reinterpret_cast<uint2*>(&smh[base + 32 * b]) = make_uint2(hi0, hi1);
                *reinterpret_cast<uint2*>(&sml[base + 32 * b]) =
                    make_uint2(pack_bf16(e0, e1), pack_bf16(e2, e3));
            }
        }
    }

    // ---- x tail of the A-row: pairs 160..191 ----
    for (int idx = tid; idx < MT * 32; idx += 256) {
        const int row = idx >> 5;
        const int pp  = idx & 31;
        const int v   = v0 + row;
        float2 w = (v < V_N)
            ? *reinterpret_cast<const float2*>(x + (size_t)v * 64 + 2 * pp)
            : make_float2(0.f, 0.f);
        const uint32_t hi = pack_bf16(w.x, w.y);
        const float h0 = __uint_as_float(hi << 16);
        const float h1 = __uint_as_float(hi & 0xffff0000u);
        smh[row * AP + 160 + pp] = hi;
        sml[row * AP + 160 + pp] = pack_bf16(w.x - h0, w.y - h1);
    }
    __syncthreads();

    // ---- phase 2: MMA ----
    float acc[2][4];
#pragma unroll
    for (int m = 0; m < 2; ++m)
        acc[m][0] = acc[m][1] = acc[m][2] = acc[m][3] = 0.f;

#pragma unroll
    for (int ks = 0; ks < 24; ++ks) {
        const int widx = ((ks * 64 + ocol) * 4 + t) * 2;
        const uint2 bhv = *reinterpret_cast<const uint2*>(&g_Wh[widx]);
        const uint2 blv = *reinterpret_cast<const uint2*>(&g_Wl[widx]);
        const uint32_t bhk[2] = {bhv.x, bhv.y};
        const uint32_t blk[2] = {blv.x, blv.y};
#pragma unroll
        for (int m = 0; m < 2; ++m) {
            const int row = m * 16 + g;
            const int c   = 8 * ks + t;
            uint32_t ah[4], al[4];
            ah[0] = smh[row * AP + c];
            ah[1] = smh[(row + 8) * AP + c];
            ah[2] = smh[row * AP + c + 4];
            ah[3] = smh[(row + 8) * AP + c + 4];
            al[0] = sml[row * AP + c];
            al[1] = sml[(row + 8) * AP + c];
            al[2] = sml[row * AP + c + 4];
            al[3] = sml[(row + 8) * AP + c + 4];
            mma_bf16(acc[m], ah, bhk);
            mma_bf16(acc[m], ah, blk);
            mma_bf16(acc[m], al, bhk);
        }
    }
    __syncthreads();

    // ---- stage msg[MT][68] (aliases sml) ----
    float* msg = reinterpret_cast<float*>(sml);
    {
        const int col = 8 * wid + 2 * t;
#pragma unroll
        for (int m = 0; m < 2; ++m) {
            const int row = m * 16 + g;
            *reinterpret_cast<float2*>(&msg[row * 68 + col])       = make_float2(acc[m][0], acc[m][1]);
            *reinterpret_cast<float2*>(&msg[(row + 8) * 68 + col]) = make_float2(acc[m][2], acc[m][3]);
        }
    }
    __syncthreads();

    // ---- phase 3: LN + nonlin + residual ----
    const float ga0 = gamma[2 * lane], ga1 = gamma[2 * lane + 1];
    const float be0 = beta[2 * lane],  be1 = beta[2 * lane + 1];

    for (int rr = 0; rr < 4; ++rr) {
        const int row = wid * 4 + rr;
        const int v   = v0 + row;
        if (v >= V_N) break;
        float2 h2 = *reinterpret_cast<const float2*>(&msg[row * 68 + 2 * lane]);
        float acc0 = h2.x, acc1 = h2.y;

        float sum = acc0 + acc1;
        float ssq = acc0 * acc0 + acc1 * acc1;
#pragma unroll
        for (int o = 16; o; o >>= 1) {
            sum += __shfl_xor_sync(0xffffffffu, sum, o);
            ssq += __shfl_xor_sync(0xffffffffu, ssq, o);
        }
        float mu  = sum * (1.f / 64.f);
        float var = ssq * (1.f / 64.f) - mu * mu;
        float rs  = rsqrtf(var + 1e-5f);
        float h0  = (acc0 - mu) * rs * ga0 + be0;
        float h1  = (acc1 - mu) * rs * ga1 + be1;

        if (lane < 8) {
            h0 = fmaxf(h0, 0.f);
            h1 = fmaxf(h1, 0.f);
        } else {
            float n  = sqrtf(h0 * h0 + h1 * h1);
            n        = fmaxf(n, 1e-8f);
            float sp = (n > 20.f) ? n : log1pf(expf(n));
            float sc = sp / n;
            h0 *= sc;
            h1 *= sc;
        }

        float2 xv = *reinterpret_cast<const float2*>(x + (size_t)v * 64 + 2 * lane);
        *reinterpret_cast<float2*>(out + (size_t)v * 64 + 2 * lane) =
            make_float2(h0 + xv.x, h1 + xv.y);
    }
}

extern "C" void kernel_launch(void* const* d_in, const int* in_sizes, int n_in,
                              void* d_out, int out_size)
{
    const float* x      = (const float*)d_in[0];
    const int*   ei     = (const int*)  d_in[1];
    const float* angles = (const float*)d_in[2];
    const float* trans  = (const float*)d_in[3];
    const float* K_self = (const float*)d_in[4];
    const float* Wn     = (const float*)d_in[5];
    const float* gamma  = (const float*)d_in[6];
    const float* beta   = (const float*)d_in[7];
    float* out = (float*)d_out;

    (void)in_sizes; (void)n_in; (void)out_size;

    pre_kernel<<<SCAN_B, 256>>>(ei, angles, trans, Wn, K_self);

    {
        const int shbytes = 2 * MT * AP * 4;   // 50176
        cudaFuncSetAttribute(fused_kernel,
                             cudaFuncAttributeMaxDynamicSharedMemorySize, shbytes);
        fused_kernel<<<(V_N + MT - 1) / MT, 256, shbytes>>>(x, gamma, beta, out);
    }
}

// round 17
// speedup vs baseline: 1.1591x; 1.1591x over previous
#include <cuda_runtime.h>
#include <math.h>
#include <stdint.h>

#define V_N 50000
#define E_N 800000
#define SCAN_B 196          /* 196*256 = 50176 >= V_N */

__device__ int    g_hist[SCAN_B * 256];
__device__ int    g_start[V_N + 1];
__device__ int    g_cursor[V_N];
__device__ int    g_bsum[SCAN_B];
__device__ int    g_done;
__device__ int    g_src[E_N];
__device__ float4 g_trig[(size_t)E_N * 2];   // sorted pos: [2p]=angle basis, [2p+1]=transporter
// W packed in mma-fragment order: index = ((ks*64 + ocol)*4 + t)*2 + r
__device__ uint32_t g_Wh[24 * 64 * 8];
__device__ uint32_t g_Wl[24 * 64 * 8];

// ---------------- helpers ----------------
__device__ __forceinline__ uint32_t pack_bf16(float e0, float e1) {
    uint32_t r;
    asm("cvt.rn.bf16x2.f32 %0, %1, %2;" : "=r"(r) : "f"(e1), "f"(e0));
    return r;
}

__device__ __forceinline__ void mma_bf16(float* d, const uint32_t* a, const uint32_t* b) {
    asm volatile(
        "mma.sync.aligned.m16n8k16.row.col.f32.bf16.bf16.f32 "
        "{%0,%1,%2,%3}, {%4,%5,%6,%7}, {%8,%9}, {%0,%1,%2,%3};"
        : "+f"(d[0]), "+f"(d[1]), "+f"(d[2]), "+f"(d[3])
        : "r"(a[0]), "r"(a[1]), "r"(a[2]), "r"(a[3]), "r"(b[0]), "r"(b[1]));
}

// ---------------- setup: zero hist + counter, pack W fragments ----------------
__global__ void setup_kernel(const float* __restrict__ Wn, const float* __restrict__ Ks) {
    const int idx = blockIdx.x * blockDim.x + threadIdx.x;
    if (idx < SCAN_B * 256) g_hist[idx] = 0;
    if (idx == 0) g_done = 0;
    if (idx < 24 * 64 * 4) {
        const int t    = idx & 3;
        const int ocol = (idx >> 2) & 63;
        const int ks   = idx >> 8;
#pragma unroll
        for (int r = 0; r < 2; ++r) {
            const int k0 = 16 * ks + 8 * r;
            const float* wp = (k0 < 320)
                ? (Wn + (k0 >> 6) * 4096 + ocol * 64 + (k0 & 63) + 2 * t)
                : (Ks + ocol * 64 + (k0 - 320) + 2 * t);
            const float2 w = *reinterpret_cast<const float2*>(wp);
            const uint32_t hi = pack_bf16(w.x, w.y);
            const float h0 = __uint_as_float(hi << 16);
            const float h1 = __uint_as_float(hi & 0xffff0000u);
            const int widx = idx * 2 + r;
            g_Wh[widx] = hi;
            g_Wl[widx] = pack_bf16(w.x - h0, w.y - h1);
        }
    }
}

__global__ void hist_kernel(const int* __restrict__ ei) {
    const int base = blockIdx.x * 512 + threadIdx.x;
    const int e0 = base, e1 = base + 256;
    int t0 = (e0 < E_N) ? ei[E_N + e0] : -1;
    int t1 = (e1 < E_N) ? ei[E_N + e1] : -1;
    if (t0 >= 0) atomicAdd(&g_hist[t0], 1);
    if (t1 >= 0) atomicAdd(&g_hist[t1], 1);
}

// ---------------- single-kernel scan (196 co-resident CTAs) ----------------
__global__ __launch_bounds__(256) void scan_kernel() {
    __shared__ int sh[256];
    __shared__ int red[256];
    const int t = threadIdx.x, b = blockIdx.x;
    const int idx = b * 256 + t;
    const int v = g_hist[idx];
    sh[t] = v;
    __syncthreads();
    for (int o = 1; o < 256; o <<= 1) {
        int u = (t >= o) ? sh[t - o] : 0;
        __syncthreads();
        sh[t] += u;
        __syncthreads();
    }
    if (t == 255) {
        g_bsum[b] = sh[255];
        __threadfence();
        atomicAdd(&g_done, 1);
    }
    if (t == 0) {
        while (atomicAdd(&g_done, 0) < SCAN_B) { }
    }
    __syncthreads();
    __threadfence();
    red[t] = (t < b) ? g_bsum[t] : 0;
    __syncthreads();
    for (int o = 128; o; o >>= 1) {
        if (t < o) red[t] += red[t + o];
        __syncthreads();
    }
    const int excl = sh[t] - v + red[0];
    if (idx < V_N) {
        g_start[idx]  = excl;
        g_cursor[idx] = excl;
        if (idx == V_N - 1) g_start[V_N] = excl + v;
    }
}

__global__ void scatter_kernel(const int* __restrict__ ei,
                               const float* __restrict__ angles,
                               const float* __restrict__ trans) {
    const int base = blockIdx.x * 512 + threadIdx.x;
#pragma unroll
    for (int q = 0; q < 2; ++q) {
        const int e = base + q * 256;
        if (e >= E_N) continue;
        const int tgt = ei[E_N + e];
        const int pos = atomicAdd(&g_cursor[tgt], 1);
        g_src[pos] = ei[e];
        float sa, ca, st, ct;
        __sincosf(angles[e], &sa, &ca);
        __sincosf(trans[e],  &st, &ct);
        g_trig[2 * pos]     = make_float4(ca, sa, fmaf(2.f * ca, ca, -1.f), 2.f * sa * ca);
        g_trig[2 * pos + 1] = make_float4(ct, st, fmaf(2.f * ct, ct, -1.f), 2.f * st * ct);
    }
}

// ---------------- fused accum + GEMM + LN + nonlin + residual ----------------
// M=16 tile -> 25KB smem, regs capped for 5 CTAs/SM (40 warps/SM).
#define AP 196   /* smem pair stride (== 4 mod 32 -> conflict-free frag loads) */
#define MT 16    /* rows per CTA */

__global__ __launch_bounds__(256, 5) void fused_kernel(
    const float* __restrict__ x,
    const float* __restrict__ gamma,
    const float* __restrict__ beta,
    float* __restrict__ out)
{
    extern __shared__ uint32_t sm[];
    uint32_t* smh = sm;                   // hi: [MT][AP]
    uint32_t* sml = sm + MT * AP;         // lo: [MT][AP] (aliased by msg later)

    const int tid  = threadIdx.x;
    const int lane = tid & 31;
    const int wid  = tid >> 5;
    const int g    = lane >> 2;
    const int t    = lane & 3;
    const int h    = lane >> 4;
    const int l    = lane & 15;
    const int v0   = blockIdx.x * MT;
    const int ocol = 8 * wid + g;

    // ---- phase 1: per-vertex S accumulation straight into smem ----
#pragma unroll 1
    for (int k = 0; k < 2; ++k) {
        const int row = 2 * wid + k;
        const int v   = v0 + row;

        float4 S0 = make_float4(0.f, 0.f, 0.f, 0.f);
        float4 S1 = S0, S2 = S0, S3 = S0, S4 = S0;

        if (v < V_N) {
            const int jb = g_start[v];
            const int je = g_start[v + 1];
            for (int j = jb + h; j < je; j += 2) {
                const int    src = g_src[j];
                const float4 A   = g_trig[2 * j];
                const float4 T   = g_trig[2 * j + 1];
                float4 f = *reinterpret_cast<const float4*>(x + (size_t)src * 64 + 4 * l);
                if (l >= 4) {
                    const float cr = (l < 12) ? T.x : T.z;
                    const float sr = (l < 12) ? T.y : T.w;
                    const float a0 = cr * f.x - sr * f.y, b0 = sr * f.x + cr * f.y;
                    const float a1 = cr * f.z - sr * f.w, b1 = sr * f.z + cr * f.w;
                    f = make_float4(a0, b0, a1, b1);
                }
                S0.x += f.x;  S0.y += f.y;  S0.z += f.z;  S0.w += f.w;
                S1.x = fmaf(A.x, f.x, S1.x); S1.y = fmaf(A.x, f.y, S1.y);
                S1.z = fmaf(A.x, f.z, S1.z); S1.w = fmaf(A.x, f.w, S1.w);
                S2.x = fmaf(A.y, f.x, S2.x); S2.y = fmaf(A.y, f.y, S2.y);
                S2.z = fmaf(A.y, f.z, S2.z); S2.w = fmaf(A.y, f.w, S2.w);
                S3.x = fmaf(A.z, f.x, S3.x); S3.y = fmaf(A.z, f.y, S3.y);
                S3.z = fmaf(A.z, f.z, S3.z); S3.w = fmaf(A.z, f.w, S3.w);
                S4.x = fmaf(A.w, f.x, S4.x); S4.y = fmaf(A.w, f.y, S4.y);
                S4.z = fmaf(A.w, f.z, S4.z); S4.w = fmaf(A.w, f.w, S4.w);
            }
        }

        // merge halves
        S0.x += __shfl_xor_sync(0xffffffffu, S0.x, 16);
        S0.y += __shfl_xor_sync(0xffffffffu, S0.y, 16);
        S0.z += __shfl_xor_sync(0xffffffffu, S0.z, 16);
        S0.w += __shfl_xor_sync(0xffffffffu, S0.w, 16);
        S1.x += __shfl_xor_sync(0xffffffffu, S1.x, 16);
        S1.y += __shfl_xor_sync(0xffffffffu, S1.y, 16);
        S1.z += __shfl_xor_sync(0xffffffffu, S1.z, 16);
        S1.w += __shfl_xor_sync(0xffffffffu, S1.w, 16);
        S2.x += __shfl_xor_sync(0xffffffffu, S2.x, 16);
        S2.y += __shfl_xor_sync(0xffffffffu, S2.y, 16);
        S2.z += __shfl_xor_sync(0xffffffffu, S2.z, 16);
        S2.w += __shfl_xor_sync(0xffffffffu, S2.w, 16);
        S3.x += __shfl_xor_sync(0xffffffffu, S3.x, 16);
        S3.y += __shfl_xor_sync(0xffffffffu, S3.y, 16);
        S3.z += __shfl_xor_sync(0xffffffffu, S3.z, 16);
        S3.w += __shfl_xor_sync(0xffffffffu, S3.w, 16);
        S4.x += __shfl_xor_sync(0xffffffffu, S4.x, 16);
        S4.y += __shfl_xor_sync(0xffffffffu, S4.y, 16);
        S4.z += __shfl_xor_sync(0xffffffffu, S4.z, 16);
        S4.w += __shfl_xor_sync(0xffffffffu, S4.w, 16);

        if (h == 0) {
            const int base = row * AP + 2 * l;
            float4 Sb[5] = {S0, S1, S2, S3, S4};
#pragma unroll
            for (int b = 0; b < 5; ++b) {
                const uint32_t hi0 = pack_bf16(Sb[b].x, Sb[b].y);
                const uint32_t hi1 = pack_bf16(Sb[b].z, Sb[b].w);
                const float e0 = Sb[b].x - __uint_as_float(hi0 << 16);
                const float e1 = Sb[b].y - __uint_as_float(hi0 & 0xffff0000u);
                const float e2 = Sb[b].z - __uint_as_float(hi1 << 16);
                const float e3 = Sb[b].w - __uint_as_float(hi1 & 0xffff0000u);
                *reinterpret_cast<uint2*>(&smh[base + 32 * b]) = make_uint2(hi0, hi1);
                *reinterpret_cast<uint2*>(&sml[base + 32 * b]) =
                    make_uint2(pack_bf16(e0, e1), pack_bf16(e2, e3));
            }
        }
    }

    // ---- x tail of the A-row: pairs 160..191 ----
    for (int idx = tid; idx < MT * 32; idx += 256) {
        const int row = idx >> 5;
        const int pp  = idx & 31;
        const int v   = v0 + row;
        float2 w = (v < V_N)
            ? *reinterpret_cast<const float2*>(x + (size_t)v * 64 + 2 * pp)
            : make_float2(0.f, 0.f);
        const uint32_t hi = pack_bf16(w.x, w.y);
        const float h0 = __uint_as_float(hi << 16);
        const float h1 = __uint_as_float(hi & 0xffff0000u);
        smh[row * AP + 160 + pp] = hi;
        sml[row * AP + 160 + pp] = pack_bf16(w.x - h0, w.y - h1);
    }
    __syncthreads();

    // ---- phase 2: MMA (16 rows -> single m16n8k16 fragment per warp) ----
    float acc[4];
    acc[0] = acc[1] = acc[2] = acc[3] = 0.f;

#pragma unroll
    for (int ks = 0; ks < 24; ++ks) {
        const int widx = ((ks * 64 + ocol) * 4 + t) * 2;
        const uint2 bhv = *reinterpret_cast<const uint2*>(&g_Wh[widx]);
        const uint2 blv = *reinterpret_cast<const uint2*>(&g_Wl[widx]);
        const uint32_t bhk[2] = {bhv.x, bhv.y};
        const uint32_t blk[2] = {blv.x, blv.y};
        const int row = g;
        const int c   = 8 * ks + t;
        uint32_t ah[4], al[4];
        ah[0] = smh[row * AP + c];
        ah[1] = smh[(row + 8) * AP + c];
        ah[2] = smh[row * AP + c + 4];
        ah[3] = smh[(row + 8) * AP + c + 4];
        al[0] = sml[row * AP + c];
        al[1] = sml[(row + 8) * AP + c];
        al[2] = sml[row * AP + c + 4];
        al[3] = sml[(row + 8) * AP + c + 4];
        mma_bf16(acc, ah, bhk);
        mma_bf16(acc, ah, blk);
        mma_bf16(acc, al, bhk);
    }
    __syncthreads();

    // ---- stage msg[MT][68] (aliases sml) ----
    float* msg = reinterpret_cast<float*>(sml);
    {
        const int col = 8 * wid + 2 * t;
        *reinterpret_cast<float2*>(&msg[g * 68 + col])       = make_float2(acc[0], acc[1]);
        *reinterpret_cast<float2*>(&msg[(g + 8) * 68 + col]) = make_float2(acc[2], acc[3]);
    }
    __syncthreads();

    // ---- phase 3: LN + nonlin + residual ----
    const float ga0 = gamma[2 * lane], ga1 = gamma[2 * lane + 1];
    const float be0 = beta[2 * lane],  be1 = beta[2 * lane + 1];

    for (int rr = 0; rr < 2; ++rr) {
        const int row = wid * 2 + rr;
        const int v   = v0 + row;
        if (v >= V_N) break;
        float2 h2 = *reinterpret_cast<const float2*>(&msg[row * 68 + 2 * lane]);
        float acc0 = h2.x, acc1 = h2.y;

        float sum = acc0 + acc1;
        float ssq = acc0 * acc0 + acc1 * acc1;
#pragma unroll
        for (int o = 16; o; o >>= 1) {
            sum += __shfl_xor_sync(0xffffffffu, sum, o);
            ssq += __shfl_xor_sync(0xffffffffu, ssq, o);
        }
        float mu  = sum * (1.f / 64.f);
        float var = ssq * (1.f / 64.f) - mu * mu;
        float rs  = rsqrtf(var + 1e-5f);
        float h0  = (acc0 - mu) * rs * ga0 + be0;
        float h1  = (acc1 - mu) * rs * ga1 + be1;

        if (lane < 8) {
            h0 = fmaxf(h0, 0.f);
            h1 = fmaxf(h1, 0.f);
        } else {
            float n  = sqrtf(h0 * h0 + h1 * h1);
            n        = fmaxf(n, 1e-8f);
            float sp = (n > 20.f) ? n : log1pf(expf(n));
            float sc = sp / n;
            h0 *= sc;
            h1 *= sc;
        }

        float2 xv = *reinterpret_cast<const float2*>(x + (size_t)v * 64 + 2 * lane);
        *reinterpret_cast<float2*>(out + (size_t)v * 64 + 2 * lane) =
            make_float2(h0 + xv.x, h1 + xv.y);
    }
}

extern "C" void kernel_launch(void* const* d_in, const int* in_sizes, int n_in,
                              void* d_out, int out_size)
{
    const float* x      = (const float*)d_in[0];
    const int*   ei     = (const int*)  d_in[1];
    const float* angles = (const float*)d_in[2];
    const float* trans  = (const float*)d_in[3];
    const float* K_self = (const float*)d_in[4];
    const float* Wn     = (const float*)d_in[5];
    const float* gamma  = (const float*)d_in[6];
    const float* beta   = (const float*)d_in[7];
    float* out = (float*)d_out;

    (void)in_sizes; (void)n_in; (void)out_size;

    setup_kernel<<<SCAN_B, 256>>>(Wn, K_self);
    hist_kernel<<<(E_N + 511) / 512, 256>>>(ei);
    scan_kernel<<<SCAN_B, 256>>>();
    scatter_kernel<<<(E_N + 511) / 512, 256>>>(ei, angles, trans);

    {
        const int shbytes = 2 * MT * AP * 4;   // 25088
        cudaFuncSetAttribute(fused_kernel,
                             cudaFuncAttributeMaxDynamicSharedMemorySize, shbytes);
        fused_kernel<<<(V_N + MT - 1) / MT, 256, shbytes>>>(x, gamma, beta, out);
    }
}